// round 14
// baseline (speedup 1.0000x reference)
#include <cuda_runtime.h>
#include <math.h>

#define B_SZ     256
#define S_LEN    1024
#define T_LEN    21
#define NFREQ    11
#define NCH      32
#define COUT     64
#define POOL_T   512
#define HID      32
#define NWROWS   46
#define FP       136     /* sfeat pitch in floats */
#define PP       68      /* sP pitch in floats */

#define L2E    1.4426950408889634f
#define TL2E   2.8853900817779268f
#define TL2E2  5.7707801635558537f

typedef unsigned long long u64t;

/* ---------------- device scratch (module-static, no runtime alloc) ------ */
__device__ __align__(16) float g_tw[T_LEN * NFREQ * 2];
__device__ __align__(16) float g_L[NWROWS * T_LEN];
__device__ __align__(16) ulonglong2 g_w01[NCH * 32];
__device__ __align__(16) u64t g_w2v[NCH * 32];
__device__ __align__(16) float g_xg[B_SZ * POOL_T * 128];

__constant__ float c_lo[8] = {
    -0.010597401784997278f,  0.032883011666982945f,  0.030841381835986965f,
    -0.18703481171888114f,  -0.02798376941698385f,   0.6308807679295904f,
     0.7148465705525415f,    0.23037781330885523f };
__constant__ float c_hi[8] = {
    -0.23037781330885523f,   0.7148465705525415f,   -0.6308807679295904f,
    -0.02798376941698385f,   0.18703481171888114f,   0.030841381835986965f,
    -0.032883011666982945f, -0.010597401784997278f };

/* ---------------- packed f32x2 + fast-math helpers ---------------------- */
static __device__ __forceinline__ u64t pk2(float a, float b) {
    u64t r;
    asm("mov.b64 %0,{%1,%2};" : "=l"(r) : "f"(a), "f"(b));
    return r;
}
static __device__ __forceinline__ void upk2(u64t v, float& a, float& b) {
    asm("mov.b64 {%0,%1},%2;" : "=f"(a), "=f"(b) : "l"(v));
}
static __device__ __forceinline__ void ffma2(u64t& d, u64t a, u64t b) {
    asm("fma.rn.f32x2 %0,%1,%2,%0;" : "+l"(d) : "l"(a), "l"(b));
}
static __device__ __forceinline__ void fadd2(u64t& d, u64t a) {
    asm("add.rn.f32x2 %0,%0,%1;" : "+l"(d) : "l"(a));
}
static __device__ __forceinline__ float ex2f(float x) {
    float r; asm("ex2.approx.f32 %0,%1;" : "=f"(r) : "f"(x)); return r;
}
static __device__ __forceinline__ float rcpf(float x) {
    float r; asm("rcp.approx.f32 %0,%1;" : "=f"(r) : "f"(x)); return r;
}
static __device__ __forceinline__ float sig_p(float zp) {
    return rcpf(1.f + ex2f(-zp));
}

/* ============ K0a: twiddles + wavelet linear map L ======================= */
__global__ void precompute_L_kernel()
{
    int tid = threadIdx.x;

    for (int i = tid; i < T_LEN * NFREQ; i += blockDim.x) {
        int n = i / NFREQ, k = i % NFREQ;
        double ang = 2.0 * (double)(k * n) / 21.0;
        g_tw[2 * i]     = (float)cospi(ang);
        g_tw[2 * i + 1] = (float)(-sinpi(ang));
    }

    if (tid < T_LEN) {
        float a[21];
        #pragma unroll
        for (int i = 0; i < 21; i++) a[i] = (i == tid) ? 1.f : 0.f;
        int n = 21;
        const int rowbase[4] = {32, 22, 14, 7};
        for (int lev = 0; lev < 4; lev++) {
            int mout = (n + 5) / 2 + 1;
            float cA[14];
            for (int m = 0; m < mout; m++) {
                float aL = 0.f, aH = 0.f;
                #pragma unroll
                for (int j = 0; j < 8; j++) {
                    int idx = 2 * m + 1 - j;
                    if (idx < 0)  idx = -idx - 1;
                    if (idx >= n) idx = 2 * n - 1 - idx;
                    aL += c_lo[j] * a[idx];
                    aH += c_hi[j] * a[idx];
                }
                cA[m] = aL;
                g_L[(rowbase[lev] + m) * T_LEN + tid] = aH;
            }
            for (int m = 0; m < mout; m++) a[m] = cA[m];
            n = mout;
        }
        for (int m = 0; m < n; m++)
            g_L[m * T_LEN + tid] = a[m];
    }
}

/* ============ K0b: weight fold, grid 32 (ci) x 32 threads (cp) =========== */
__global__ void __launch_bounds__(32) precompute_fold_kernel(
    const float* __restrict__ conv_w)
{
    __shared__ float sL[NWROWS];

    int ci = blockIdx.x;
    int cp = threadIdx.x;

    if (ci < T_LEN) {
        for (int j = cp; j < NWROWS; j += 32)
            sL[j] = g_L[j * T_LEN + ci];
    }
    __syncwarp();

    float vlo[3], vhi[3];
    #pragma unroll
    for (int k = 0; k < 3; k++) {
        vlo[k] = conv_w[(cp * 78 + ci) * 3 + k];
        vhi[k] = conv_w[((cp + 32) * 78 + ci) * 3 + k];
    }
    if (ci < T_LEN) {
        const float* wl = conv_w + (cp * 78 + 32) * 3;
        const float* wh = conv_w + ((cp + 32) * 78 + 32) * 3;
        #pragma unroll 2
        for (int j = 0; j < NWROWS; j++) {
            float l = sL[j];
            #pragma unroll
            for (int k = 0; k < 3; k++) {
                vlo[k] = fmaf(wl[j * 3 + k], l, vlo[k]);
                vhi[k] = fmaf(wh[j * 3 + k], l, vhi[k]);
            }
        }
    }
    ulonglong2 w01;
    w01.x = pk2(vlo[0], vhi[0]);
    w01.y = pk2(vlo[1], vhi[1]);
    g_w01[ci * 32 + cp] = w01;
    g_w2v[ci * 32 + cp] = pk2(vlo[2], vhi[2]);
}

/* ============ K1: fused feat + conv + xg GEMM, 128-col tiles ============= */
/* smem (u64 units):
   sfeat [0, 2176)       : 32ch x 136 plain floats (128 cols + halo + pad)
   sw01  [2176, 4224)    : conv taps k0,k1
   sw2v  [4224, 5248)    : conv tap k2
   sW    [5248, 9472)    : xg weights [k=64][pitch 66]
   sP    [9472, 11648)   : pooled tile floats [k=64][pitch 68]
   stw   [11648, 11879)  : DFT twiddles
   total 95032 B -> 2 CTAs/SM                                               */
#define SM_SW01  2176
#define SM_SW2V  4224
#define SM_SW    5248
#define SM_SP    9472
#define SM_STW   11648
#define SM_TOTAL_U64 11879

__global__ void __launch_bounds__(512) fused_kernel(
    const float* __restrict__ x,   const float* __restrict__ conv_b,
    const float* __restrict__ w_ih, const float* __restrict__ b_ih,
    const float* __restrict__ b_hh)
{
    extern __shared__ u64t sm[];
    float*      sfeat = (float*)sm;
    ulonglong2* sw01  = (ulonglong2*)(sm + SM_SW01);
    u64t*       sw2v  = sm + SM_SW2V;
    u64t*       sW    = sm + SM_SW;
    float*      sP    = (float*)(sm + SM_SP);
    float*      stw   = (float*)(sm + SM_STW);

    int tid = threadIdx.x;
    int b   = blockIdx.x >> 3;
    int q   = blockIdx.x & 7;
    int s0  = q * 128;

    /* ---- phase 0: stage all weights/twiddles ---- */
    for (int i = tid; i < NCH * 32; i += 512) {
        sw01[i] = g_w01[i];
        sw2v[i] = g_w2v[i];
    }
    for (int i = tid; i < T_LEN * NFREQ * 2; i += 512)
        stw[i] = g_tw[i];
    for (int idx = tid; idx < 64 * 64; idx += 512) {
        int k = idx >> 6, cp = idx & 63;
        int j = cp >> 1, g0 = (cp & 1) * 2;
        float s0f = (cp & 1) ? TL2E : L2E;
        sW[k * 66 + cp] = pk2(w_ih[(g0 * 32 + j) * 64 + k] * s0f,
                              w_ih[((g0 + 1) * 32 + j) * 64 + k] * L2E);
    }
    __syncthreads();

    /* ---- phase 1: features, 2 threads per column (130 cols) ---- */
    {
        int col  = tid >> 1;
        int half = tid & 1;
        if (col < 130) {
            int s = s0 + col - 1;
            if (s >= 0 && s < S_LEN) {
                const float* xp = x + (size_t)(b * S_LEN + s) * T_LEN;
                float xr[T_LEN];
                #pragma unroll
                for (int i = 0; i < T_LEN; i++) xr[i] = xp[i];

                if (half == 0) {
                    #pragma unroll
                    for (int i = 0; i < 11; i++)
                        sfeat[i * FP + col] = xr[i];
                    #pragma unroll
                    for (int k = 0; k < 6; k++) {
                        float re = 0.f, im = 0.f;
                        #pragma unroll
                        for (int n = 0; n < T_LEN; n++) {
                            re = fmaf(xr[n], stw[(n * NFREQ + k) * 2],     re);
                            im = fmaf(xr[n], stw[(n * NFREQ + k) * 2 + 1], im);
                        }
                        sfeat[(T_LEN + k) * FP + col] = sqrtf(re * re + im * im);
                    }
                } else {
                    #pragma unroll
                    for (int i = 11; i < T_LEN; i++)
                        sfeat[i * FP + col] = xr[i];
                    #pragma unroll
                    for (int k = 6; k < NFREQ; k++) {
                        float re = 0.f, im = 0.f;
                        #pragma unroll
                        for (int n = 0; n < T_LEN; n++) {
                            re = fmaf(xr[n], stw[(n * NFREQ + k) * 2],     re);
                            im = fmaf(xr[n], stw[(n * NFREQ + k) * 2 + 1], im);
                        }
                        sfeat[(T_LEN + k) * FP + col] = sqrtf(re * re + im * im);
                    }
                }
            } else {
                if (half == 0) {
                    #pragma unroll
                    for (int i = 0; i < 11; i++)  sfeat[i * FP + col] = 0.f;
                    #pragma unroll
                    for (int k = 0; k < 6; k++)   sfeat[(T_LEN + k) * FP + col] = 0.f;
                } else {
                    #pragma unroll
                    for (int i = 11; i < T_LEN; i++) sfeat[i * FP + col] = 0.f;
                    #pragma unroll
                    for (int k = 6; k < NFREQ; k++)  sfeat[(T_LEN + k) * FP + col] = 0.f;
                }
            }
        }
    }
    __syncthreads();

    /* ---- phase 2: conv3 + ReLU + maxpool2 -> sP[ch][t] ---- */
    {
        int cp = tid & 31;
        int sg = tid >> 5;          /* 0..15, each: 8 conv cols -> 4 pooled */
        int cs = sg * 8;

        u64t bias2 = pk2(conv_b[cp], conv_b[cp + 32]);
        u64t acc[8];
        #pragma unroll
        for (int i = 0; i < 8; i++) acc[i] = bias2;

        for (int ci = 0; ci < NCH; ci++) {
            const float* vpf = sfeat + ci * FP + cs;
            float4 f0 = *(const float4*)(vpf);
            float4 f1 = *(const float4*)(vpf + 4);
            float2 f2 = *(const float2*)(vpf + 8);
            float vv[10] = { f0.x, f0.y, f0.z, f0.w,
                             f1.x, f1.y, f1.z, f1.w, f2.x, f2.y };
            u64t v[10];
            #pragma unroll
            for (int i = 0; i < 10; i++) v[i] = pk2(vv[i], vv[i]);

            ulonglong2 w01 = sw01[ci * 32 + cp];
            u64t       wk2 = sw2v[ci * 32 + cp];
            #pragma unroll
            for (int i = 0; i < 8; i++) {
                ffma2(acc[i], w01.x, v[i]);
                ffma2(acc[i], w01.y, v[i + 1]);
                ffma2(acc[i], wk2,   v[i + 2]);
            }
        }

        int t0l = sg * 4;
        #pragma unroll
        for (int i = 0; i < 4; i++) {
            float l0, h0, l1, h1;
            upk2(acc[2 * i],     l0, h0);
            upk2(acc[2 * i + 1], l1, h1);
            sP[cp * PP + t0l + i]        = fmaxf(fmaxf(l0, l1), 0.f);
            sP[(cp + 32) * PP + t0l + i] = fmaxf(fmaxf(h0, h1), 0.f);
        }
    }
    __syncthreads();

    /* ---- phase 3: xg GEMM, 256 threads, 4-row x 4-colpair tiles -------- */
    if (tid < 256) {
        int tx = tid & 15, ty = tid >> 4;    /* ty 0..15 */
        int r0 = ty * 4;                     /* rows 0..63 */

        u64t acc[4][4];
        #pragma unroll
        for (int i = 0; i < 4; i++)
            #pragma unroll
            for (int qq = 0; qq < 4; qq++) acc[i][qq] = 0ull;

        #pragma unroll 4
        for (int k = 0; k < 64; k++) {
            const float* ar = sP + k * PP + r0;
            float4 av0 = *(const float4*)ar;
            u64t ad[4] = { pk2(av0.x, av0.x), pk2(av0.y, av0.y),
                           pk2(av0.z, av0.z), pk2(av0.w, av0.w) };
            const u64t* wr = sW + k * 66 + tx;
            u64t wv[4] = { wr[0], wr[16], wr[32], wr[48] };
            #pragma unroll
            for (int i = 0; i < 4; i++)
                #pragma unroll
                for (int qq = 0; qq < 4; qq++)
                    ffma2(acc[i][qq], ad[i], wv[qq]);
        }

        float* outp = g_xg + ((size_t)b * POOL_T + q * 64) * 128;
        #pragma unroll
        for (int qq = 0; qq < 4; qq++) {
            int cp = tx + qq * 16;
            int j = cp >> 1, g0 = (cp & 1) * 2;
            int gi0 = g0 * 32 + j, gi1 = (g0 + 1) * 32 + j;
            float s0f = (cp & 1) ? TL2E : L2E;
            u64t bp = pk2((b_ih[gi0] + b_hh[gi0]) * s0f,
                          (b_ih[gi1] + b_hh[gi1]) * L2E);
            #pragma unroll
            for (int i = 0; i < 4; i++) {
                u64t s = acc[i][qq];
                fadd2(s, bp);
                float lo, hi;
                upk2(s, lo, hi);
                *(float2*)(outp + (size_t)(r0 + i) * 128 + cp * 2) = make_float2(lo, hi);
            }
        }
    }
}

/* ============ K3: LSTM v5.1 (best known recurrence, unchanged) =========== */
__global__ void __launch_bounds__(64) lstm5_kernel(
    const float* __restrict__ w_hh, const float* __restrict__ fc_w,
    const float* __restrict__ fc_b, float* __restrict__ out)
{
    __shared__ __align__(16) float s_h[2][2][32];

    int w = threadIdx.x >> 5;
    int j = threadIdx.x & 31;
    int b = blockIdx.x * 2 + w;

    const float sc[4] = { L2E, L2E, TL2E, L2E };
    u64t w2[4][16];
    #pragma unroll
    for (int g = 0; g < 4; g++) {
        const float4* row = (const float4*)(w_hh + (g * 32 + j) * 32);
        #pragma unroll
        for (int q = 0; q < 8; q++) {
            float4 v = row[q];
            w2[g][2 * q]     = pk2(v.x * sc[g], v.y * sc[g]);
            w2[g][2 * q + 1] = pk2(v.z * sc[g], v.w * sc[g]);
        }
    }

    s_h[w][0][j] = 0.f;
    float c = 0.f, h = 0.f;

    const ulonglong2* xgp = (const ulonglong2*)(g_xg + (size_t)b * POOL_T * 128);
    ulonglong2 pre[4];
    #pragma unroll
    for (int u = 0; u < 4; u++) pre[u] = xgp[u * 32 + j];
    __syncwarp();

    for (int t = 0; t < POOL_T; t += 4) {
        #pragma unroll
        for (int u = 0; u < 4; u++) {
            int tt = t + u;
            ulonglong2 z4 = pre[u];
            int tn = tt + 4;
            if (tn > POOL_T - 1) tn = POOL_T - 1;
            pre[u] = xgp[(size_t)tn * 32 + j];

            const ulonglong2* hp = (const ulonglong2*)s_h[w][tt & 1];

            u64t a0 = z4.x & 0xffffffffull, a1 = z4.x >> 32;
            u64t a2 = z4.y & 0xffffffffull, a3 = z4.y >> 32;
            u64t b0 = 0, b1 = 0, b2 = 0, b3 = 0;
            u64t d0 = 0, d1 = 0, d2 = 0, d3 = 0;
            u64t e0 = 0, e1 = 0, e2 = 0, e3 = 0;

            #pragma unroll
            for (int kq = 0; kq < 4; kq++) {
                ulonglong2 h2 = hp[kq];
                ffma2(a0, w2[0][2 * kq], h2.x);
                ffma2(a1, w2[1][2 * kq], h2.x);
                ffma2(a2, w2[2][2 * kq], h2.x);
                ffma2(a3, w2[3][2 * kq], h2.x);
                ffma2(d0, w2[0][2 * kq + 1], h2.y);
                ffma2(d1, w2[1][2 * kq + 1], h2.y);
                ffma2(d2, w2[2][2 * kq + 1], h2.y);
                ffma2(d3, w2[3][2 * kq + 1], h2.y);
            }
            #pragma unroll
            for (int kq = 4; kq < 8; kq++) {
                ulonglong2 h2 = hp[kq];
                ffma2(b0, w2[0][2 * kq], h2.x);
                ffma2(b1, w2[1][2 * kq], h2.x);
                ffma2(b2, w2[2][2 * kq], h2.x);
                ffma2(b3, w2[3][2 * kq], h2.x);
                ffma2(e0, w2[0][2 * kq + 1], h2.y);
                ffma2(e1, w2[1][2 * kq + 1], h2.y);
                ffma2(e2, w2[2][2 * kq + 1], h2.y);
                ffma2(e3, w2[3][2 * kq + 1], h2.y);
            }
            fadd2(a0, b0); fadd2(d0, e0); fadd2(a0, d0);
            fadd2(a1, b1); fadd2(d1, e1); fadd2(a1, d1);
            fadd2(a2, b2); fadd2(d2, e2); fadd2(a2, d2);
            fadd2(a3, b3); fadd2(d3, e3); fadd2(a3, d3);

            float lo, hi;
            upk2(a0, lo, hi); float zi = lo + hi;
            upk2(a1, lo, hi); float zf = lo + hi;
            upk2(a2, lo, hi); float zg = lo + hi;
            upk2(a3, lo, hi); float zo = lo + hi;

            float ai = sig_p(zi), af = sig_p(zf);
            float ao = sig_p(zo);
            float agS = fmaf(-TL2E2, rcpf(1.f + ex2f(zg)), TL2E);
            c = fmaf(af, c, ai * agS);
            h = ao * fmaf(-2.f, rcpf(1.f + ex2f(c)), 1.f);

            s_h[w][(tt & 1) ^ 1][j] = h;
            __syncwarp();
        }
    }

    float v = fc_w[j] * h;
    #pragma unroll
    for (int off = 16; off; off >>= 1)
        v += __shfl_down_sync(0xffffffffu, v, off);
    if (j == 0) out[b] = v + fc_b[0];
}

/* ======================================================================== */
extern "C" void kernel_launch(void* const* d_in, const int* in_sizes, int n_in,
                              void* d_out, int out_size)
{
    const float* x      = (const float*)d_in[0];
    const float* conv_w = (const float*)d_in[1];
    const float* conv_b = (const float*)d_in[2];
    const float* w_ih   = (const float*)d_in[3];
    const float* w_hh   = (const float*)d_in[4];
    const float* b_ih   = (const float*)d_in[5];
    const float* b_hh   = (const float*)d_in[6];
    const float* fc_w   = (const float*)d_in[7];
    const float* fc_b   = (const float*)d_in[8];
    float* out = (float*)d_out;

    precompute_L_kernel<<<1, 64>>>();
    precompute_fold_kernel<<<NCH, 32>>>(conv_w);

    size_t smem_f = (size_t)SM_TOTAL_U64 * sizeof(u64t);
    cudaFuncSetAttribute(fused_kernel,
                         cudaFuncAttributeMaxDynamicSharedMemorySize, (int)smem_f);
    fused_kernel<<<B_SZ * 8, 512, smem_f>>>(x, conv_b, w_ih, b_ih, b_hh);

    lstm5_kernel<<<B_SZ / 2, 64>>>(w_hh, fc_w, fc_b, out);
}

// round 16
// speedup vs baseline: 1.2579x; 1.2579x over previous
#include <cuda_runtime.h>
#include <cuda_bf16.h>
#include <math.h>

#define B_SZ     256
#define S_LEN    1024
#define T_LEN    21
#define NFREQ    11
#define NCH      32
#define COUT     64
#define POOL_T   512
#define HID      32
#define NWROWS   46
#define FPITCH   264     /* sfeat pitch in floats */
#define AP       72      /* bf16 MMA-plane pitch (rows of 144 B) */

#define L2E    1.4426950408889634f
#define TL2E   2.8853900817779268f
#define TL2E2  5.7707801635558537f

typedef unsigned long long u64t;

/* ---------------- device scratch ---------------------------------------- */
__device__ __align__(16) float g_tw[T_LEN * NFREQ * 2];
__device__ __align__(16) float g_L[NWROWS * T_LEN];
__device__ __align__(16) ulonglong2 g_w01[NCH * 32];
__device__ __align__(16) u64t g_w2v[NCH * 32];
__device__ __align__(16) float g_xg[B_SZ * POOL_T * 128];

__constant__ float c_lo[8] = {
    -0.010597401784997278f,  0.032883011666982945f,  0.030841381835986965f,
    -0.18703481171888114f,  -0.02798376941698385f,   0.6308807679295904f,
     0.7148465705525415f,    0.23037781330885523f };
__constant__ float c_hi[8] = {
    -0.23037781330885523f,   0.7148465705525415f,   -0.6308807679295904f,
    -0.02798376941698385f,   0.18703481171888114f,   0.030841381835986965f,
    -0.032883011666982945f, -0.010597401784997278f };

/* ---------------- packed f32x2 + fast-math helpers ---------------------- */
static __device__ __forceinline__ u64t pk2(float a, float b) {
    u64t r;
    asm("mov.b64 %0,{%1,%2};" : "=l"(r) : "f"(a), "f"(b));
    return r;
}
static __device__ __forceinline__ void upk2(u64t v, float& a, float& b) {
    asm("mov.b64 {%0,%1},%2;" : "=f"(a), "=f"(b) : "l"(v));
}
static __device__ __forceinline__ void ffma2(u64t& d, u64t a, u64t b) {
    asm("fma.rn.f32x2 %0,%1,%2,%0;" : "+l"(d) : "l"(a), "l"(b));
}
static __device__ __forceinline__ void fadd2(u64t& d, u64t a) {
    asm("add.rn.f32x2 %0,%0,%1;" : "+l"(d) : "l"(a));
}
static __device__ __forceinline__ float ex2f(float x) {
    float r; asm("ex2.approx.f32 %0,%1;" : "=f"(r) : "f"(x)); return r;
}
static __device__ __forceinline__ float rcpf(float x) {
    float r; asm("rcp.approx.f32 %0,%1;" : "=f"(r) : "f"(x)); return r;
}
static __device__ __forceinline__ float sig_p(float zp) {
    return rcpf(1.f + ex2f(-zp));
}

/* ---------------- warp MMA m16n8k16 bf16 -------------------------------- */
static __device__ __forceinline__ void mma16816(float* c,
    unsigned a0, unsigned a1, unsigned a2, unsigned a3,
    unsigned b0, unsigned b1)
{
    asm volatile(
        "mma.sync.aligned.m16n8k16.row.col.f32.bf16.bf16.f32 "
        "{%0,%1,%2,%3}, {%4,%5,%6,%7}, {%8,%9}, {%0,%1,%2,%3};"
        : "+f"(c[0]), "+f"(c[1]), "+f"(c[2]), "+f"(c[3])
        : "r"(a0), "r"(a1), "r"(a2), "r"(a3), "r"(b0), "r"(b1));
}

/* ============ K0a: twiddles + wavelet linear map L ======================= */
__global__ void precompute_L_kernel()
{
    int tid = threadIdx.x;

    for (int i = tid; i < T_LEN * NFREQ; i += blockDim.x) {
        int n = i / NFREQ, k = i % NFREQ;
        double ang = 2.0 * (double)(k * n) / 21.0;
        g_tw[2 * i]     = (float)cospi(ang);
        g_tw[2 * i + 1] = (float)(-sinpi(ang));
    }

    if (tid < T_LEN) {
        float a[21];
        #pragma unroll
        for (int i = 0; i < 21; i++) a[i] = (i == tid) ? 1.f : 0.f;
        int n = 21;
        const int rowbase[4] = {32, 22, 14, 7};
        for (int lev = 0; lev < 4; lev++) {
            int mout = (n + 5) / 2 + 1;
            float cA[14];
            for (int m = 0; m < mout; m++) {
                float aL = 0.f, aH = 0.f;
                #pragma unroll
                for (int j = 0; j < 8; j++) {
                    int idx = 2 * m + 1 - j;
                    if (idx < 0)  idx = -idx - 1;
                    if (idx >= n) idx = 2 * n - 1 - idx;
                    aL += c_lo[j] * a[idx];
                    aH += c_hi[j] * a[idx];
                }
                cA[m] = aL;
                g_L[(rowbase[lev] + m) * T_LEN + tid] = aH;
            }
            for (int m = 0; m < mout; m++) a[m] = cA[m];
            n = mout;
        }
        for (int m = 0; m < n; m++)
            g_L[m * T_LEN + tid] = a[m];
    }
}

/* ============ K0b: weight fold =========================================== */
__global__ void __launch_bounds__(32) precompute_fold_kernel(
    const float* __restrict__ conv_w)
{
    __shared__ float sL[NWROWS];

    int ci = blockIdx.x;
    int cp = threadIdx.x;

    if (ci < T_LEN) {
        for (int j = cp; j < NWROWS; j += 32)
            sL[j] = g_L[j * T_LEN + ci];
    }
    __syncwarp();

    float vlo[3], vhi[3];
    #pragma unroll
    for (int k = 0; k < 3; k++) {
        vlo[k] = conv_w[(cp * 78 + ci) * 3 + k];
        vhi[k] = conv_w[((cp + 32) * 78 + ci) * 3 + k];
    }
    if (ci < T_LEN) {
        const float* wl = conv_w + (cp * 78 + 32) * 3;
        const float* wh = conv_w + ((cp + 32) * 78 + 32) * 3;
        #pragma unroll 2
        for (int j = 0; j < NWROWS; j++) {
            float l = sL[j];
            #pragma unroll
            for (int k = 0; k < 3; k++) {
                vlo[k] = fmaf(wl[j * 3 + k], l, vlo[k]);
                vhi[k] = fmaf(wh[j * 3 + k], l, vhi[k]);
            }
        }
    }
    ulonglong2 w01;
    w01.x = pk2(vlo[0], vhi[0]);
    w01.y = pk2(vlo[1], vhi[1]);
    g_w01[ci * 32 + cp] = w01;
    g_w2v[ci * 32 + cp] = pk2(vlo[2], vhi[2]);
}

/* ============ K1: fused feat + conv(FFMA2) + xg GEMM(mma.sync) =========== */
/* smem (u64 units):
   sfeat [0, 4224)        32x264 floats
   sw01  [4224, 6272)     conv taps k0,k1
   sw2v  [6272, 7296)     conv tap k2
   sAh   [7296, 9600)     P hi-plane  [128 t][AP] bf16
   sAl   [9600, 11904)    P lo-plane
   sBh   [11904, 14208)   W hi-plane  [128 n][AP] bf16
   sBl   [14208, 16512)   W lo-plane
   stw   [16512, 16743)   twiddles
   sbias [16744, 16808)   128 floats                                        */
#define SM_SW01  4224
#define SM_SW2V  6272
#define SM_AH    7296
#define SM_AL    9600
#define SM_BH    11904
#define SM_BL    14208
#define SM_STW   16512
#define SM_BIAS  16744
#define SM_TOTAL_U64 16808

__global__ void __launch_bounds__(512) fused_kernel(
    const float* __restrict__ x,   const float* __restrict__ conv_b,
    const float* __restrict__ w_ih, const float* __restrict__ b_ih,
    const float* __restrict__ b_hh)
{
    extern __shared__ u64t sm[];
    float*         sfeat = (float*)sm;
    ulonglong2*    sw01  = (ulonglong2*)(sm + SM_SW01);
    u64t*          sw2v  = sm + SM_SW2V;
    __nv_bfloat16* sAh   = (__nv_bfloat16*)(sm + SM_AH);
    __nv_bfloat16* sAl   = (__nv_bfloat16*)(sm + SM_AL);
    __nv_bfloat16* sBh   = (__nv_bfloat16*)(sm + SM_BH);
    __nv_bfloat16* sBl   = (__nv_bfloat16*)(sm + SM_BL);
    float*         stw   = (float*)(sm + SM_STW);
    float*         sbias = (float*)(sm + SM_BIAS);

    int tid = threadIdx.x;
    int b   = blockIdx.x >> 2;
    int q   = blockIdx.x & 3;
    int s0  = q * 256;

    const float sc4[4] = { L2E, L2E, TL2E, L2E };

    /* ---- phase 0: stage conv weights, twiddles, split-bf16 W, bias ---- */
    for (int i = tid; i < NCH * 32; i += 512) {
        sw01[i] = g_w01[i];
        sw2v[i] = g_w2v[i];
    }
    for (int i = tid; i < T_LEN * NFREQ * 2; i += 512)
        stw[i] = g_tw[i];
    for (int idx = tid; idx < 128 * 64; idx += 512) {
        int row = idx >> 6, k = idx & 63;      /* row = 4j+gate */
        int j = row >> 2, gate = row & 3;
        float wv = w_ih[(gate * 32 + j) * 64 + k] * sc4[gate];
        __nv_bfloat16 wh = __float2bfloat16(wv);
        sBh[row * AP + k] = wh;
        sBl[row * AP + k] = __float2bfloat16(wv - __bfloat162float(wh));
    }
    if (tid < 128) {
        int j = tid >> 2, gate = tid & 3;
        sbias[tid] = (b_ih[gate * 32 + j] + b_hh[gate * 32 + j]) * sc4[gate];
    }
    __syncthreads();

    /* ---- phase 1: features (raw + |rfft|) ---- */
    {
        bool isA = (tid < 258);
        int col  = isA ? tid : (tid - 254);
        int s    = s0 + col - 1;
        if (s >= 0 && s < S_LEN) {
            const float* xp = x + (size_t)(b * S_LEN + s) * T_LEN;
            float xr[T_LEN];
            #pragma unroll
            for (int i = 0; i < T_LEN; i++) xr[i] = xp[i];

            if (isA) {
                #pragma unroll
                for (int i = 0; i < T_LEN; i++)
                    sfeat[i * FPITCH + col] = xr[i];
                #pragma unroll
                for (int k = 0; k < 6; k++) {
                    float re = 0.f, im = 0.f;
                    #pragma unroll
                    for (int n = 0; n < T_LEN; n++) {
                        re = fmaf(xr[n], stw[(n * NFREQ + k) * 2],     re);
                        im = fmaf(xr[n], stw[(n * NFREQ + k) * 2 + 1], im);
                    }
                    sfeat[(T_LEN + k) * FPITCH + col] = sqrtf(re * re + im * im);
                }
            }
            if (!isA || tid < 4) {
                #pragma unroll
                for (int k = 6; k < NFREQ; k++) {
                    float re = 0.f, im = 0.f;
                    #pragma unroll
                    for (int n = 0; n < T_LEN; n++) {
                        re = fmaf(xr[n], stw[(n * NFREQ + k) * 2],     re);
                        im = fmaf(xr[n], stw[(n * NFREQ + k) * 2 + 1], im);
                    }
                    sfeat[(T_LEN + k) * FPITCH + col] = sqrtf(re * re + im * im);
                }
            }
        } else {
            if (isA) {
                #pragma unroll
                for (int ci = 0; ci < NCH; ci++)
                    sfeat[ci * FPITCH + col] = 0.f;
            } else {
                #pragma unroll
                for (int k = 6; k < NFREQ; k++)
                    sfeat[(T_LEN + k) * FPITCH + col] = 0.f;
            }
        }
    }
    __syncthreads();

    /* ---- phase 2: conv3 + ReLU + maxpool2 -> split-bf16 A planes ---- */
    {
        int cp = tid & 31;
        int sg = tid >> 5;
        int cs = sg * 16;

        u64t bias2 = pk2(conv_b[cp], conv_b[cp + 32]);
        u64t acc[16];
        #pragma unroll
        for (int i = 0; i < 16; i++) acc[i] = bias2;

        for (int ci = 0; ci < NCH; ci++) {
            const float* vpf = sfeat + ci * FPITCH + cs;
            float4 f0 = *(const float4*)(vpf);
            float4 f1 = *(const float4*)(vpf + 4);
            float4 f2 = *(const float4*)(vpf + 8);
            float4 f3 = *(const float4*)(vpf + 12);
            float2 f4 = *(const float2*)(vpf + 16);
            float vv[18] = { f0.x, f0.y, f0.z, f0.w, f1.x, f1.y, f1.z, f1.w,
                             f2.x, f2.y, f2.z, f2.w, f3.x, f3.y, f3.z, f3.w,
                             f4.x, f4.y };
            u64t v[18];
            #pragma unroll
            for (int i = 0; i < 18; i++) v[i] = pk2(vv[i], vv[i]);

            ulonglong2 w01 = sw01[ci * 32 + cp];
            u64t       wk2 = sw2v[ci * 32 + cp];
            #pragma unroll
            for (int i = 0; i < 16; i++) {
                ffma2(acc[i], w01.x, v[i]);
                ffma2(acc[i], w01.y, v[i + 1]);
                ffma2(acc[i], wk2,   v[i + 2]);
            }
        }

        int t0l = sg * 8;
        #pragma unroll
        for (int i = 0; i < 8; i++) {
            float l0, h0, l1, h1;
            upk2(acc[2 * i],     l0, h0);
            upk2(acc[2 * i + 1], l1, h1);
            float p0 = fmaxf(fmaxf(l0, l1), 0.f);       /* channel cp    */
            float p1 = fmaxf(fmaxf(h0, h1), 0.f);       /* channel cp+32 */
            int t = t0l + i;
            __nv_bfloat16 h0b = __float2bfloat16(p0);
            __nv_bfloat16 h1b = __float2bfloat16(p1);
            sAh[t * AP + cp]      = h0b;
            sAh[t * AP + cp + 32] = h1b;
            sAl[t * AP + cp]      = __float2bfloat16(p0 - __bfloat162float(h0b));
            sAl[t * AP + cp + 32] = __float2bfloat16(p1 - __bfloat162float(h1b));
        }
    }
    __syncthreads();

    /* ---- phase 3: warp MMA  D = Ah*Bh + Ah*Bl + Al*Bh  (all 16 warps) -- */
    {
        int w    = tid >> 5;
        int lane = tid & 31;
        int g    = lane >> 2;
        int tig  = lane & 3;
        int rbase  = (w >> 1) * 16;
        int cbase0 = (w & 1) * 64;

        float acc[8][4];
        #pragma unroll
        for (int ct = 0; ct < 8; ct++)
            #pragma unroll
            for (int i = 0; i < 4; i++) acc[ct][i] = 0.f;

        #pragma unroll
        for (int ks = 0; ks < 4; ks++) {
            int kb = ks * 16;
            int ar = (rbase + g) * AP + kb + 2 * tig;
            unsigned a0 = *(const unsigned*)(sAh + ar);
            unsigned a1 = *(const unsigned*)(sAh + ar + 8 * AP);
            unsigned a2 = *(const unsigned*)(sAh + ar + 8);
            unsigned a3 = *(const unsigned*)(sAh + ar + 8 * AP + 8);
            unsigned l0 = *(const unsigned*)(sAl + ar);
            unsigned l1 = *(const unsigned*)(sAl + ar + 8 * AP);
            unsigned l2 = *(const unsigned*)(sAl + ar + 8);
            unsigned l3 = *(const unsigned*)(sAl + ar + 8 * AP + 8);

            #pragma unroll
            for (int ct = 0; ct < 8; ct++) {
                int br = (cbase0 + ct * 8 + g) * AP + kb + 2 * tig;
                unsigned b0  = *(const unsigned*)(sBh + br);
                unsigned b1  = *(const unsigned*)(sBh + br + 8);
                unsigned bl0 = *(const unsigned*)(sBl + br);
                unsigned bl1 = *(const unsigned*)(sBl + br + 8);
                mma16816(acc[ct], a0, a1, a2, a3, b0, b1);
                mma16816(acc[ct], a0, a1, a2, a3, bl0, bl1);
                mma16816(acc[ct], l0, l1, l2, l3, b0, b1);
            }
        }

        float* outp = g_xg + ((size_t)b * POOL_T + q * 128) * 128;
        int r0_ = rbase + g;
        #pragma unroll
        for (int ct = 0; ct < 8; ct++) {
            int n0 = cbase0 + ct * 8 + tig * 2;
            float bb0 = sbias[n0], bb1 = sbias[n0 + 1];
            *(float2*)(outp + (size_t)r0_ * 128 + n0) =
                make_float2(acc[ct][0] + bb0, acc[ct][1] + bb1);
            *(float2*)(outp + (size_t)(r0_ + 8) * 128 + n0) =
                make_float2(acc[ct][2] + bb0, acc[ct][3] + bb1);
        }
    }
}

/* ============ K3: LSTM v5.1 (best known recurrence, unchanged) =========== */
__global__ void __launch_bounds__(64) lstm5_kernel(
    const float* __restrict__ w_hh, const float* __restrict__ fc_w,
    const float* __restrict__ fc_b, float* __restrict__ out)
{
    __shared__ __align__(16) float s_h[2][2][32];

    int w = threadIdx.x >> 5;
    int j = threadIdx.x & 31;
    int b = blockIdx.x * 2 + w;

    const float sc[4] = { L2E, L2E, TL2E, L2E };
    u64t w2[4][16];
    #pragma unroll
    for (int g = 0; g < 4; g++) {
        const float4* row = (const float4*)(w_hh + (g * 32 + j) * 32);
        #pragma unroll
        for (int q = 0; q < 8; q++) {
            float4 v = row[q];
            w2[g][2 * q]     = pk2(v.x * sc[g], v.y * sc[g]);
            w2[g][2 * q + 1] = pk2(v.z * sc[g], v.w * sc[g]);
        }
    }

    s_h[w][0][j] = 0.f;
    float c = 0.f, h = 0.f;

    const ulonglong2* xgp = (const ulonglong2*)(g_xg + (size_t)b * POOL_T * 128);
    ulonglong2 pre[4];
    #pragma unroll
    for (int u = 0; u < 4; u++) pre[u] = xgp[u * 32 + j];
    __syncwarp();

    for (int t = 0; t < POOL_T; t += 4) {
        #pragma unroll
        for (int u = 0; u < 4; u++) {
            int tt = t + u;
            ulonglong2 z4 = pre[u];
            int tn = tt + 4;
            if (tn > POOL_T - 1) tn = POOL_T - 1;
            pre[u] = xgp[(size_t)tn * 32 + j];

            const ulonglong2* hp = (const ulonglong2*)s_h[w][tt & 1];

            u64t a0 = z4.x & 0xffffffffull, a1 = z4.x >> 32;
            u64t a2 = z4.y & 0xffffffffull, a3 = z4.y >> 32;
            u64t b0 = 0, b1 = 0, b2 = 0, b3 = 0;
            u64t d0 = 0, d1 = 0, d2 = 0, d3 = 0;
            u64t e0 = 0, e1 = 0, e2 = 0, e3 = 0;

            #pragma unroll
            for (int kq = 0; kq < 4; kq++) {
                ulonglong2 h2 = hp[kq];
                ffma2(a0, w2[0][2 * kq], h2.x);
                ffma2(a1, w2[1][2 * kq], h2.x);
                ffma2(a2, w2[2][2 * kq], h2.x);
                ffma2(a3, w2[3][2 * kq], h2.x);
                ffma2(d0, w2[0][2 * kq + 1], h2.y);
                ffma2(d1, w2[1][2 * kq + 1], h2.y);
                ffma2(d2, w2[2][2 * kq + 1], h2.y);
                ffma2(d3, w2[3][2 * kq + 1], h2.y);
            }
            #pragma unroll
            for (int kq = 4; kq < 8; kq++) {
                ulonglong2 h2 = hp[kq];
                ffma2(b0, w2[0][2 * kq], h2.x);
                ffma2(b1, w2[1][2 * kq], h2.x);
                ffma2(b2, w2[2][2 * kq], h2.x);
                ffma2(b3, w2[3][2 * kq], h2.x);
                ffma2(e0, w2[0][2 * kq + 1], h2.y);
                ffma2(e1, w2[1][2 * kq + 1], h2.y);
                ffma2(e2, w2[2][2 * kq + 1], h2.y);
                ffma2(e3, w2[3][2 * kq + 1], h2.y);
            }
            fadd2(a0, b0); fadd2(d0, e0); fadd2(a0, d0);
            fadd2(a1, b1); fadd2(d1, e1); fadd2(a1, d1);
            fadd2(a2, b2); fadd2(d2, e2); fadd2(a2, d2);
            fadd2(a3, b3); fadd2(d3, e3); fadd2(a3, d3);

            float lo, hi;
            upk2(a0, lo, hi); float zi = lo + hi;
            upk2(a1, lo, hi); float zf = lo + hi;
            upk2(a2, lo, hi); float zg = lo + hi;
            upk2(a3, lo, hi); float zo = lo + hi;

            float ai = sig_p(zi), af = sig_p(zf);
            float ao = sig_p(zo);
            float agS = fmaf(-TL2E2, rcpf(1.f + ex2f(zg)), TL2E);
            c = fmaf(af, c, ai * agS);
            h = ao * fmaf(-2.f, rcpf(1.f + ex2f(c)), 1.f);

            s_h[w][(tt & 1) ^ 1][j] = h;
            __syncwarp();
        }
    }

    float v = fc_w[j] * h;
    #pragma unroll
    for (int off = 16; off; off >>= 1)
        v += __shfl_down_sync(0xffffffffu, v, off);
    if (j == 0) out[b] = v + fc_b[0];
}

/* ======================================================================== */
extern "C" void kernel_launch(void* const* d_in, const int* in_sizes, int n_in,
                              void* d_out, int out_size)
{
    const float* x      = (const float*)d_in[0];
    const float* conv_w = (const float*)d_in[1];
    const float* conv_b = (const float*)d_in[2];
    const float* w_ih   = (const float*)d_in[3];
    const float* w_hh   = (const float*)d_in[4];
    const float* b_ih   = (const float*)d_in[5];
    const float* b_hh   = (const float*)d_in[6];
    const float* fc_w   = (const float*)d_in[7];
    const float* fc_b   = (const float*)d_in[8];
    float* out = (float*)d_out;

    precompute_L_kernel<<<1, 64>>>();
    precompute_fold_kernel<<<NCH, 32>>>(conv_w);

    size_t smem_f = (size_t)SM_TOTAL_U64 * sizeof(u64t);
    cudaFuncSetAttribute(fused_kernel,
                         cudaFuncAttributeMaxDynamicSharedMemorySize, (int)smem_f);
    fused_kernel<<<B_SZ * 4, 512, smem_f>>>(x, conv_b, w_ih, b_ih, b_hh);

    lstm5_kernel<<<B_SZ / 2, 64>>>(w_hh, fc_w, fc_b, out);
}

// round 17
// speedup vs baseline: 1.2982x; 1.0320x over previous
#include <cuda_runtime.h>
#include <cuda_bf16.h>
#include <math.h>

#define B_SZ     256
#define S_LEN    1024
#define T_LEN    21
#define NFREQ    11
#define NCH      32
#define COUT     64
#define POOL_T   512
#define HID      32
#define NWROWS   46
#define AP       72      /* xg-plane pitch (bf16) */
#define FP2      40      /* feature/convW plane pitch (bf16) */

#define L2E    1.4426950408889634f
#define TL2E   2.8853900817779268f
#define TL2E2  5.7707801635558537f

typedef unsigned long long u64t;

/* ---------------- device scratch ---------------------------------------- */
__device__ __align__(16) float g_tw[T_LEN * NFREQ * 2];
__device__ __align__(16) float g_L[NWROWS * T_LEN];
__device__ __align__(16) ulonglong2 g_w01[NCH * 32];
__device__ __align__(16) u64t g_w2v[NCH * 32];
__device__ __align__(16) float g_xg[B_SZ * POOL_T * 128];

__constant__ float c_lo[8] = {
    -0.010597401784997278f,  0.032883011666982945f,  0.030841381835986965f,
    -0.18703481171888114f,  -0.02798376941698385f,   0.6308807679295904f,
     0.7148465705525415f,    0.23037781330885523f };
__constant__ float c_hi[8] = {
    -0.23037781330885523f,   0.7148465705525415f,   -0.6308807679295904f,
    -0.02798376941698385f,   0.18703481171888114f,   0.030841381835986965f,
    -0.032883011666982945f, -0.010597401784997278f };

/* ---------------- helpers ----------------------------------------------- */
static __device__ __forceinline__ u64t pk2(float a, float b) {
    u64t r;
    asm("mov.b64 %0,{%1,%2};" : "=l"(r) : "f"(a), "f"(b));
    return r;
}
static __device__ __forceinline__ void upk2(u64t v, float& a, float& b) {
    asm("mov.b64 {%0,%1},%2;" : "=f"(a), "=f"(b) : "l"(v));
}
static __device__ __forceinline__ void ffma2(u64t& d, u64t a, u64t b) {
    asm("fma.rn.f32x2 %0,%1,%2,%0;" : "+l"(d) : "l"(a), "l"(b));
}
static __device__ __forceinline__ void fadd2(u64t& d, u64t a) {
    asm("add.rn.f32x2 %0,%0,%1;" : "+l"(d) : "l"(a));
}
static __device__ __forceinline__ float ex2f(float x) {
    float r; asm("ex2.approx.f32 %0,%1;" : "=f"(r) : "f"(x)); return r;
}
static __device__ __forceinline__ float rcpf(float x) {
    float r; asm("rcp.approx.f32 %0,%1;" : "=f"(r) : "f"(x)); return r;
}
static __device__ __forceinline__ float sig_p(float zp) {
    return rcpf(1.f + ex2f(-zp));
}
static __device__ __forceinline__ void mma16816(float* c,
    unsigned a0, unsigned a1, unsigned a2, unsigned a3,
    unsigned b0, unsigned b1)
{
    asm volatile(
        "mma.sync.aligned.m16n8k16.row.col.f32.bf16.bf16.f32 "
        "{%0,%1,%2,%3}, {%4,%5,%6,%7}, {%8,%9}, {%0,%1,%2,%3};"
        : "+f"(c[0]), "+f"(c[1]), "+f"(c[2]), "+f"(c[3])
        : "r"(a0), "r"(a1), "r"(a2), "r"(a3), "r"(b0), "r"(b1));
}
static __device__ __forceinline__ void splitbf(float v,
    __nv_bfloat16* ph, __nv_bfloat16* pl)
{
    __nv_bfloat16 h = __float2bfloat16(v);
    *ph = h;
    *pl = __float2bfloat16(v - __bfloat162float(h));
}

/* ============ K0a: twiddles + wavelet linear map L ======================= */
__global__ void precompute_L_kernel()
{
    int tid = threadIdx.x;

    for (int i = tid; i < T_LEN * NFREQ; i += blockDim.x) {
        int n = i / NFREQ, k = i % NFREQ;
        double ang = 2.0 * (double)(k * n) / 21.0;
        g_tw[2 * i]     = (float)cospi(ang);
        g_tw[2 * i + 1] = (float)(-sinpi(ang));
    }

    if (tid < T_LEN) {
        float a[21];
        #pragma unroll
        for (int i = 0; i < 21; i++) a[i] = (i == tid) ? 1.f : 0.f;
        int n = 21;
        const int rowbase[4] = {32, 22, 14, 7};
        for (int lev = 0; lev < 4; lev++) {
            int mout = (n + 5) / 2 + 1;
            float cA[14];
            for (int m = 0; m < mout; m++) {
                float aL = 0.f, aH = 0.f;
                #pragma unroll
                for (int j = 0; j < 8; j++) {
                    int idx = 2 * m + 1 - j;
                    if (idx < 0)  idx = -idx - 1;
                    if (idx >= n) idx = 2 * n - 1 - idx;
                    aL += c_lo[j] * a[idx];
                    aH += c_hi[j] * a[idx];
                }
                cA[m] = aL;
                g_L[(rowbase[lev] + m) * T_LEN + tid] = aH;
            }
            for (int m = 0; m < mout; m++) a[m] = cA[m];
            n = mout;
        }
        for (int m = 0; m < n; m++)
            g_L[m * T_LEN + tid] = a[m];
    }
}

/* ============ K0b: weight fold =========================================== */
__global__ void __launch_bounds__(32) precompute_fold_kernel(
    const float* __restrict__ conv_w)
{
    __shared__ float sL[NWROWS];

    int ci = blockIdx.x;
    int cp = threadIdx.x;

    if (ci < T_LEN) {
        for (int j = cp; j < NWROWS; j += 32)
            sL[j] = g_L[j * T_LEN + ci];
    }
    __syncwarp();

    float vlo[3], vhi[3];
    #pragma unroll
    for (int k = 0; k < 3; k++) {
        vlo[k] = conv_w[(cp * 78 + ci) * 3 + k];
        vhi[k] = conv_w[((cp + 32) * 78 + ci) * 3 + k];
    }
    if (ci < T_LEN) {
        const float* wl = conv_w + (cp * 78 + 32) * 3;
        const float* wh = conv_w + ((cp + 32) * 78 + 32) * 3;
        #pragma unroll 2
        for (int j = 0; j < NWROWS; j++) {
            float l = sL[j];
            #pragma unroll
            for (int k = 0; k < 3; k++) {
                vlo[k] = fmaf(wl[j * 3 + k], l, vlo[k]);
                vhi[k] = fmaf(wh[j * 3 + k], l, vhi[k]);
            }
        }
    }
    ulonglong2 w01;
    w01.x = pk2(vlo[0], vhi[0]);
    w01.y = pk2(vlo[1], vhi[1]);
    g_w01[ci * 32 + cp] = w01;
    g_w2v[ci * 32 + cp] = pk2(vlo[2], vhi[2]);
}

/* ============ K1: fused feat + conv(MMA) + xg GEMM(MMA) ================== */
/* smem (u64 units):
   sFh   [0, 2580)        F hi  [258 s][FP2] bf16
   sFl   [2580, 5160)     F lo
   sWch  [5160, 7080)     conv W hi [3 tap][64 c][FP2] bf16
   sWcl  [7080, 9000)     conv W lo
   sAh   [9000, 11304)    pooled hi [128 t][AP]
   sAl   [11304, 13608)   pooled lo
   sBh   [13608, 15912)   xg W hi [128 n][AP]
   sBl   [15912, 18216)   xg W lo
   stw   [18216, 18447)   twiddles
   sxb   [18448, 18512)   xg bias (128 f)
   scb   [18512, 18544)   conv bias (64 f)                                  */
#define SM_FH    0
#define SM_FL    2580
#define SM_WCH   5160
#define SM_WCL   7080
#define SM_AH    9000
#define SM_AL    11304
#define SM_BH    13608
#define SM_BL    15912
#define SM_STW   18216
#define SM_XB    18448
#define SM_CB    18512
#define SM_TOTAL_U64 18544

__global__ void __launch_bounds__(512) fused_kernel(
    const float* __restrict__ x,   const float* __restrict__ conv_b,
    const float* __restrict__ w_ih, const float* __restrict__ b_ih,
    const float* __restrict__ b_hh)
{
    extern __shared__ u64t sm[];
    __nv_bfloat16* sFh  = (__nv_bfloat16*)(sm + SM_FH);
    __nv_bfloat16* sFl  = (__nv_bfloat16*)(sm + SM_FL);
    __nv_bfloat16* sWch = (__nv_bfloat16*)(sm + SM_WCH);
    __nv_bfloat16* sWcl = (__nv_bfloat16*)(sm + SM_WCL);
    __nv_bfloat16* sAh  = (__nv_bfloat16*)(sm + SM_AH);
    __nv_bfloat16* sAl  = (__nv_bfloat16*)(sm + SM_AL);
    __nv_bfloat16* sBh  = (__nv_bfloat16*)(sm + SM_BH);
    __nv_bfloat16* sBl  = (__nv_bfloat16*)(sm + SM_BL);
    float*         stw  = (float*)(sm + SM_STW);
    float*         sxb  = (float*)(sm + SM_XB);
    float*         scb  = (float*)(sm + SM_CB);

    int tid = threadIdx.x;
    int b   = blockIdx.x >> 2;
    int q   = blockIdx.x & 3;
    int s0  = q * 256;

    const float sc4[4] = { L2E, L2E, TL2E, L2E };

    /* ---- phase 0: stage everything ---- */
    for (int i = tid; i < T_LEN * NFREQ * 2; i += 512)
        stw[i] = g_tw[i];
    /* conv weights -> split bf16 planes [tap][c][ci] */
    for (int idx = tid; idx < 3 * 64 * 32; idx += 512) {
        int tap = idx >> 11, rem = idx & 2047;
        int c = rem >> 5, ci = rem & 31;
        int cp = c & 31;
        float wlo_, whi_;
        if (tap < 2) {
            ulonglong2 p = g_w01[ci * 32 + cp];
            upk2(tap == 0 ? p.x : p.y, wlo_, whi_);
        } else {
            upk2(g_w2v[ci * 32 + cp], wlo_, whi_);
        }
        float wv = (c < 32) ? wlo_ : whi_;
        int o = (tap * 64 + c) * FP2 + ci;
        splitbf(wv, sWch + o, sWcl + o);
    }
    /* xg W -> split bf16 [128 n=4j+gate][64 k] prescaled */
    for (int idx = tid; idx < 128 * 64; idx += 512) {
        int row = idx >> 6, k = idx & 63;
        int j = row >> 2, gate = row & 3;
        float wv = w_ih[(gate * 32 + j) * 64 + k] * sc4[gate];
        splitbf(wv, sBh + row * AP + k, sBl + row * AP + k);
    }
    if (tid < 128) {
        int j = tid >> 2, gate = tid & 3;
        sxb[tid] = (b_ih[gate * 32 + j] + b_hh[gate * 32 + j]) * sc4[gate];
    }
    if (tid < 64) scb[tid] = conv_b[tid];
    __syncthreads();

    /* ---- phase 1: features -> split-bf16 F[s_local][ci] ---- */
    {
        bool isA = (tid < 258);
        int col  = isA ? tid : (tid - 254);
        int s    = s0 + col - 1;
        if (s >= 0 && s < S_LEN) {
            const float* xp = x + (size_t)(b * S_LEN + s) * T_LEN;
            float xr[T_LEN];
            #pragma unroll
            for (int i = 0; i < T_LEN; i++) xr[i] = xp[i];

            if (isA) {
                #pragma unroll
                for (int i = 0; i < T_LEN; i++)
                    splitbf(xr[i], sFh + col * FP2 + i, sFl + col * FP2 + i);
                #pragma unroll
                for (int k = 0; k < 6; k++) {
                    float re = 0.f, im = 0.f;
                    #pragma unroll
                    for (int n = 0; n < T_LEN; n++) {
                        re = fmaf(xr[n], stw[(n * NFREQ + k) * 2],     re);
                        im = fmaf(xr[n], stw[(n * NFREQ + k) * 2 + 1], im);
                    }
                    float m = sqrtf(re * re + im * im);
                    splitbf(m, sFh + col * FP2 + T_LEN + k,
                               sFl + col * FP2 + T_LEN + k);
                }
            }
            if (!isA || tid < 4) {
                #pragma unroll
                for (int k = 6; k < NFREQ; k++) {
                    float re = 0.f, im = 0.f;
                    #pragma unroll
                    for (int n = 0; n < T_LEN; n++) {
                        re = fmaf(xr[n], stw[(n * NFREQ + k) * 2],     re);
                        im = fmaf(xr[n], stw[(n * NFREQ + k) * 2 + 1], im);
                    }
                    float m = sqrtf(re * re + im * im);
                    splitbf(m, sFh + col * FP2 + T_LEN + k,
                               sFl + col * FP2 + T_LEN + k);
                }
            }
        } else {
            if (isA) {
                #pragma unroll
                for (int ci = 0; ci < NCH; ci++) {
                    sFh[col * FP2 + ci] = __float2bfloat16(0.f);
                    sFl[col * FP2 + ci] = __float2bfloat16(0.f);
                }
            } else {
                #pragma unroll
                for (int k = 6; k < NFREQ; k++) {
                    sFh[col * FP2 + T_LEN + k] = __float2bfloat16(0.f);
                    sFl[col * FP2 + T_LEN + k] = __float2bfloat16(0.f);
                }
            }
        }
    }
    __syncthreads();

    /* ---- phase 2: conv3 via 3 shifted MMA GEMMs + ReLU + maxpool ------- */
    {
        int w    = tid >> 5;
        int lane = tid & 31;
        int g    = lane >> 2;
        int tig  = lane & 3;
        int rbase = w * 16;            /* s_local rows rbase..rbase+15 */

        float acc[8][4];
        #pragma unroll
        for (int ct = 0; ct < 8; ct++) {
            int n0 = ct * 8 + tig * 2;
            acc[ct][0] = scb[n0];
            acc[ct][1] = scb[n0 + 1];
            acc[ct][2] = scb[n0];
            acc[ct][3] = scb[n0 + 1];
        }

        #pragma unroll
        for (int tap = 0; tap < 3; tap++) {
            const __nv_bfloat16* Wh = sWch + tap * 64 * FP2;
            const __nv_bfloat16* Wl = sWcl + tap * 64 * FP2;
            #pragma unroll
            for (int ks = 0; ks < 2; ks++) {
                int kb = ks * 16;
                int ar = (rbase + tap + g) * FP2 + kb + 2 * tig;
                unsigned a0 = *(const unsigned*)(sFh + ar);
                unsigned a1 = *(const unsigned*)(sFh + ar + 8 * FP2);
                unsigned a2 = *(const unsigned*)(sFh + ar + 8);
                unsigned a3 = *(const unsigned*)(sFh + ar + 8 * FP2 + 8);
                unsigned l0 = *(const unsigned*)(sFl + ar);
                unsigned l1 = *(const unsigned*)(sFl + ar + 8 * FP2);
                unsigned l2 = *(const unsigned*)(sFl + ar + 8);
                unsigned l3 = *(const unsigned*)(sFl + ar + 8 * FP2 + 8);

                #pragma unroll
                for (int ct = 0; ct < 8; ct++) {
                    int br = (ct * 8 + g) * FP2 + kb + 2 * tig;
                    unsigned b0  = *(const unsigned*)(Wh + br);
                    unsigned b1  = *(const unsigned*)(Wh + br + 8);
                    unsigned bl0 = *(const unsigned*)(Wl + br);
                    unsigned bl1 = *(const unsigned*)(Wl + br + 8);
                    mma16816(acc[ct], a0, a1, a2, a3, b0, b1);
                    mma16816(acc[ct], a0, a1, a2, a3, bl0, bl1);
                    mma16816(acc[ct], l0, l1, l2, l3, b0, b1);
                }
            }
        }

        /* ReLU + maxpool(s pairs) via shfl, write split-bf16 to sA planes */
        int t0 = (rbase >> 1) + (g >> 1);
        #pragma unroll
        for (int ct = 0; ct < 8; ct++) {
            float r0 = fmaxf(acc[ct][0], 0.f);
            float r1 = fmaxf(acc[ct][1], 0.f);
            float r2 = fmaxf(acc[ct][2], 0.f);
            float r3 = fmaxf(acc[ct][3], 0.f);
            float p0 = fmaxf(r0, __shfl_xor_sync(0xffffffffu, r0, 4));
            float p1 = fmaxf(r1, __shfl_xor_sync(0xffffffffu, r1, 4));
            float p2 = fmaxf(r2, __shfl_xor_sync(0xffffffffu, r2, 4));
            float p3 = fmaxf(r3, __shfl_xor_sync(0xffffffffu, r3, 4));
            if (!(g & 1)) {
                int n0 = ct * 8 + tig * 2;
                splitbf(p0, sAh + t0 * AP + n0,       sAl + t0 * AP + n0);
                splitbf(p1, sAh + t0 * AP + n0 + 1,   sAl + t0 * AP + n0 + 1);
                splitbf(p2, sAh + (t0 + 4) * AP + n0, sAl + (t0 + 4) * AP + n0);
                splitbf(p3, sAh + (t0 + 4) * AP + n0 + 1,
                            sAl + (t0 + 4) * AP + n0 + 1);
            }
        }
    }
    __syncthreads();

    /* ---- phase 3: xg GEMM (split-bf16 MMA, as round 16) ---- */
    {
        int w    = tid >> 5;
        int lane = tid & 31;
        int g    = lane >> 2;
        int tig  = lane & 3;
        int rbase  = (w >> 1) * 16;
        int cbase0 = (w & 1) * 64;

        float acc[8][4];
        #pragma unroll
        for (int ct = 0; ct < 8; ct++)
            #pragma unroll
            for (int i = 0; i < 4; i++) acc[ct][i] = 0.f;

        #pragma unroll
        for (int ks = 0; ks < 4; ks++) {
            int kb = ks * 16;
            int ar = (rbase + g) * AP + kb + 2 * tig;
            unsigned a0 = *(const unsigned*)(sAh + ar);
            unsigned a1 = *(const unsigned*)(sAh + ar + 8 * AP);
            unsigned a2 = *(const unsigned*)(sAh + ar + 8);
            unsigned a3 = *(const unsigned*)(sAh + ar + 8 * AP + 8);
            unsigned l0 = *(const unsigned*)(sAl + ar);
            unsigned l1 = *(const unsigned*)(sAl + ar + 8 * AP);
            unsigned l2 = *(const unsigned*)(sAl + ar + 8);
            unsigned l3 = *(const unsigned*)(sAl + ar + 8 * AP + 8);

            #pragma unroll
            for (int ct = 0; ct < 8; ct++) {
                int br = (cbase0 + ct * 8 + g) * AP + kb + 2 * tig;
                unsigned b0  = *(const unsigned*)(sBh + br);
                unsigned b1  = *(const unsigned*)(sBh + br + 8);
                unsigned bl0 = *(const unsigned*)(sBl + br);
                unsigned bl1 = *(const unsigned*)(sBl + br + 8);
                mma16816(acc[ct], a0, a1, a2, a3, b0, b1);
                mma16816(acc[ct], a0, a1, a2, a3, bl0, bl1);
                mma16816(acc[ct], l0, l1, l2, l3, b0, b1);
            }
        }

        float* outp = g_xg + ((size_t)b * POOL_T + q * 128) * 128;
        int r0_ = rbase + g;
        #pragma unroll
        for (int ct = 0; ct < 8; ct++) {
            int n0 = cbase0 + ct * 8 + tig * 2;
            float bb0 = sxb[n0], bb1 = sxb[n0 + 1];
            *(float2*)(outp + (size_t)r0_ * 128 + n0) =
                make_float2(acc[ct][0] + bb0, acc[ct][1] + bb1);
            *(float2*)(outp + (size_t)(r0_ + 8) * 128 + n0) =
                make_float2(acc[ct][2] + bb0, acc[ct][3] + bb1);
        }
    }
}

/* ============ K3: LSTM v5.1 (best known recurrence, unchanged) =========== */
__global__ void __launch_bounds__(64) lstm5_kernel(
    const float* __restrict__ w_hh, const float* __restrict__ fc_w,
    const float* __restrict__ fc_b, float* __restrict__ out)
{
    __shared__ __align__(16) float s_h[2][2][32];

    int w = threadIdx.x >> 5;
    int j = threadIdx.x & 31;
    int b = blockIdx.x * 2 + w;

    const float sc[4] = { L2E, L2E, TL2E, L2E };
    u64t w2[4][16];
    #pragma unroll
    for (int g = 0; g < 4; g++) {
        const float4* row = (const float4*)(w_hh + (g * 32 + j) * 32);
        #pragma unroll
        for (int q = 0; q < 8; q++) {
            float4 v = row[q];
            w2[g][2 * q]     = pk2(v.x * sc[g], v.y * sc[g]);
            w2[g][2 * q + 1] = pk2(v.z * sc[g], v.w * sc[g]);
        }
    }

    s_h[w][0][j] = 0.f;
    float c = 0.f, h = 0.f;

    const ulonglong2* xgp = (const ulonglong2*)(g_xg + (size_t)b * POOL_T * 128);
    ulonglong2 pre[4];
    #pragma unroll
    for (int u = 0; u < 4; u++) pre[u] = xgp[u * 32 + j];
    __syncwarp();

    for (int t = 0; t < POOL_T; t += 4) {
        #pragma unroll
        for (int u = 0; u < 4; u++) {
            int tt = t + u;
            ulonglong2 z4 = pre[u];
            int tn = tt + 4;
            if (tn > POOL_T - 1) tn = POOL_T - 1;
            pre[u] = xgp[(size_t)tn * 32 + j];

            const ulonglong2* hp = (const ulonglong2*)s_h[w][tt & 1];

            u64t a0 = z4.x & 0xffffffffull, a1 = z4.x >> 32;
            u64t a2 = z4.y & 0xffffffffull, a3 = z4.y >> 32;
            u64t b0 = 0, b1 = 0, b2 = 0, b3 = 0;
            u64t d0 = 0, d1 = 0, d2 = 0, d3 = 0;
            u64t e0 = 0, e1 = 0, e2 = 0, e3 = 0;

            #pragma unroll
            for (int kq = 0; kq < 4; kq++) {
                ulonglong2 h2 = hp[kq];
                ffma2(a0, w2[0][2 * kq], h2.x);
                ffma2(a1, w2[1][2 * kq], h2.x);
                ffma2(a2, w2[2][2 * kq], h2.x);
                ffma2(a3, w2[3][2 * kq], h2.x);
                ffma2(d0, w2[0][2 * kq + 1], h2.y);
                ffma2(d1, w2[1][2 * kq + 1], h2.y);
                ffma2(d2, w2[2][2 * kq + 1], h2.y);
                ffma2(d3, w2[3][2 * kq + 1], h2.y);
            }
            #pragma unroll
            for (int kq = 4; kq < 8; kq++) {
                ulonglong2 h2 = hp[kq];
                ffma2(b0, w2[0][2 * kq], h2.x);
                ffma2(b1, w2[1][2 * kq], h2.x);
                ffma2(b2, w2[2][2 * kq], h2.x);
                ffma2(b3, w2[3][2 * kq], h2.x);
                ffma2(e0, w2[0][2 * kq + 1], h2.y);
                ffma2(e1, w2[1][2 * kq + 1], h2.y);
                ffma2(e2, w2[2][2 * kq + 1], h2.y);
                ffma2(e3, w2[3][2 * kq + 1], h2.y);
            }
            fadd2(a0, b0); fadd2(d0, e0); fadd2(a0, d0);
            fadd2(a1, b1); fadd2(d1, e1); fadd2(a1, d1);
            fadd2(a2, b2); fadd2(d2, e2); fadd2(a2, d2);
            fadd2(a3, b3); fadd2(d3, e3); fadd2(a3, d3);

            float lo, hi;
            upk2(a0, lo, hi); float zi = lo + hi;
            upk2(a1, lo, hi); float zf = lo + hi;
            upk2(a2, lo, hi); float zg = lo + hi;
            upk2(a3, lo, hi); float zo = lo + hi;

            float ai = sig_p(zi), af = sig_p(zf);
            float ao = sig_p(zo);
            float agS = fmaf(-TL2E2, rcpf(1.f + ex2f(zg)), TL2E);
            c = fmaf(af, c, ai * agS);
            h = ao * fmaf(-2.f, rcpf(1.f + ex2f(c)), 1.f);

            s_h[w][(tt & 1) ^ 1][j] = h;
            __syncwarp();
        }
    }

    float v = fc_w[j] * h;
    #pragma unroll
    for (int off = 16; off; off >>= 1)
        v += __shfl_down_sync(0xffffffffu, v, off);
    if (j == 0) out[b] = v + fc_b[0];
}

/* ======================================================================== */
extern "C" void kernel_launch(void* const* d_in, const int* in_sizes, int n_in,
                              void* d_out, int out_size)
{
    const float* x      = (const float*)d_in[0];
    const float* conv_w = (const float*)d_in[1];
    const float* conv_b = (const float*)d_in[2];
    const float* w_ih   = (const float*)d_in[3];
    const float* w_hh   = (const float*)d_in[4];
    const float* b_ih   = (const float*)d_in[5];
    const float* b_hh   = (const float*)d_in[6];
    const float* fc_w   = (const float*)d_in[7];
    const float* fc_b   = (const float*)d_in[8];
    float* out = (float*)d_out;

    precompute_L_kernel<<<1, 64>>>();
    precompute_fold_kernel<<<NCH, 32>>>(conv_w);

    size_t smem_f = (size_t)SM_TOTAL_U64 * sizeof(u64t);
    cudaFuncSetAttribute(fused_kernel,
                         cudaFuncAttributeMaxDynamicSharedMemorySize, (int)smem_f);
    fused_kernel<<<B_SZ * 4, 512, smem_f>>>(x, conv_b, w_ih, b_ih, b_hh);

    lstm5_kernel<<<B_SZ / 2, 64>>>(w_hh, fc_w, fc_b, out);
}